// round 1
// baseline (speedup 1.0000x reference)
#include <cuda_runtime.h>
#include <stdint.h>
#include <math.h>

// Problem constants
#define ND 4       // digits
#define NS 2048    // samples
#define NBATCH 512
#define ALPHA_C 0.1f

// RNG mode: 1 = jax_threefry_partitionable (default in modern JAX), 0 = legacy
#define PARTITIONABLE 1

// scratch: n1_summed per (b,s)
__device__ int g_n1sum[NBATCH * NS];

// ---------------------------------------------------------------------------
// threefry2x32 (device)
// ---------------------------------------------------------------------------
__device__ __forceinline__ void tf2x32_d(uint32_t k0, uint32_t k1,
                                         uint32_t c0, uint32_t c1,
                                         uint32_t& o0, uint32_t& o1) {
    uint32_t ks2 = 0x1BD11BDAu ^ k0 ^ k1;
    uint32_t x0 = c0 + k0, x1 = c1 + k1;
#define TF_RND(r) { x0 += x1; x1 = __funnelshift_l(x1, x1, (r)); x1 ^= x0; }
    TF_RND(13) TF_RND(15) TF_RND(26) TF_RND(6)
    x0 += k1;  x1 += ks2 + 1u;
    TF_RND(17) TF_RND(29) TF_RND(16) TF_RND(24)
    x0 += ks2; x1 += k0 + 2u;
    TF_RND(13) TF_RND(15) TF_RND(26) TF_RND(6)
    x0 += k0;  x1 += k1 + 3u;
    TF_RND(17) TF_RND(29) TF_RND(16) TF_RND(24)
    x0 += k1;  x1 += ks2 + 4u;
    TF_RND(13) TF_RND(15) TF_RND(26) TF_RND(6)
    x0 += ks2; x1 += k0 + 5u;
#undef TF_RND
    o0 = x0; o1 = x1;
}

// ---------------------------------------------------------------------------
// Accurate float log (musl logf, ~1 ulp) — immune to --use_fast_math rewrites.
// Valid for normal positive x.
// ---------------------------------------------------------------------------
__device__ __forceinline__ float alogf(float x) {
    uint32_t ix = __float_as_uint(x);
    ix += 0x3f800000u - 0x3f3504f3u;
    int k = (int)(ix >> 23) - 127;
    ix = (ix & 0x007fffffu) + 0x3f3504f3u;
    float xm = __uint_as_float(ix);
    float f = xm - 1.0f;
    float s = f / (2.0f + f);
    float z = s * s;
    float w = z * z;
    float t1 = w * (0.40000972152f + w * 0.24279078841f);
    float t2 = z * (0.66666662693f + w * 0.28498786688f);
    float R = t2 + t1;
    float hfsq = 0.5f * f * f;
    float dk = (float)k;
    return s * (hfsq + R) + dk * 9.0580006145e-06f - hfsq + f
           + dk * 0.69313812256f;
}

__device__ __forceinline__ float gumbel_from_bits(uint32_t bits) {
    // JAX uniform(minval=tiny, maxval=1): u = max(bitcast(bits>>9|1.0f)-1, tiny)
    float f = __uint_as_float((bits >> 9) | 0x3f800000u) - 1.0f;
    float u = fmaxf(f, 1.17549435e-38f);
    float t = -alogf(u);
    return -alogf(t);
}

// ---------------------------------------------------------------------------
// Main sampler: one thread per (b, s). Digit chain fully unrolled.
// ---------------------------------------------------------------------------
__global__ void __launch_bounds__(256)
sampler_kernel(const float* __restrict__ n1_logits,   // [B, D, 10]
               const float* __restrict__ counters,    // [D, 10]
               const int*   __restrict__ s_arr,       // [B]
               float* __restrict__ out,
               uint4 ka, uint4 kb) {
    __shared__ float sp[ND * 10];  // probs base: logits - alpha*log(counters)
    __shared__ int   sd[ND];       // decimal digits of s[b]
    __shared__ int   ssv;

    const int b = blockIdx.y;
    const int t = threadIdx.x;

    if (t < ND * 10)
        sp[t] = n1_logits[b * (ND * 10) + t] - ALPHA_C * alogf(counters[t]);
    if (t == 0) {
        int sv = s_arr[b];
        ssv = sv;
        sd[0] = sv / 1000;
        sd[1] = (sv / 100) % 10;
        sd[2] = (sv / 10) % 10;
        sd[3] = sv % 10;
    }
    __syncthreads();

    const int sidx = blockIdx.x * 256 + t;
    const uint32_t base = (uint32_t)(b * NS + sidx) * 10u;

    const uint32_t K[8] = {ka.x, ka.y, ka.z, ka.w, kb.x, kb.y, kb.z, kb.w};

    int constraint = 0;
    int samp[ND];

#pragma unroll
    for (int i = 0; i < ND; i++) {
        const int mx = sd[i];
        const uint32_t k0 = K[2 * i], k1 = K[2 * i + 1];
        float best = -1e30f;
        int arg = 0;
#pragma unroll
        for (int c = 0; c < 10; c++) {
            // invalid & unconstrained -> -inf in ref: never wins, skip cipher.
            if (constraint || c <= mx) {
                uint32_t o0, o1;
#if PARTITIONABLE
                tf2x32_d(k0, k1, 0u, base + (uint32_t)c, o0, o1);
                uint32_t bits = o0 ^ o1;
#else
                // legacy mode: pairing (j, j+half); lane0 for b<B/2, lane1 else
                const uint32_t half = (uint32_t)(NBATCH / 2) * NS * 10u;
                uint32_t j = base + (uint32_t)c;
                uint32_t bits;
                if (j < half) { tf2x32_d(k0, k1, j, j + half, o0, o1); bits = o0; }
                else          { tf2x32_d(k0, k1, j - half, j, o0, o1); bits = o1; }
#endif
                float v = sp[i * 10 + c] + gumbel_from_bits(bits);
                if (v > best) { best = v; arg = c; }
            }
        }
        samp[i] = arg;
        constraint |= (arg != mx);
    }

    const int n1 = samp[0] * 1000 + samp[1] * 100 + samp[2] * 10 + samp[3];
    const int n2 = ssv - n1;   // in [0, 10000)

    const int lin = b * NS + sidx;
    g_n1sum[lin] = n1;

    // Output layout (float32 concat): n1_samples[B,S,D,1] | n2d[B,S,D,1] | weights[B,S]
    float4* out_n1 = (float4*)out;
    float4* out_n2 = (float4*)(out + (size_t)NBATCH * NS * ND);
    out_n1[lin] = make_float4((float)samp[0], (float)samp[1],
                              (float)samp[2], (float)samp[3]);
    // sorted-shift trick == plain decimal digits of n2
    out_n2[lin] = make_float4((float)(n2 / 1000), (float)((n2 / 100) % 10),
                              (float)((n2 / 10) % 10), (float)(n2 % 10));
}

// ---------------------------------------------------------------------------
// Per-row histogram (10^4 bins in smem) + gather -> weights
// ---------------------------------------------------------------------------
__global__ void __launch_bounds__(256)
hist_kernel(float* __restrict__ w) {
    __shared__ int h[10000];
    const int b = blockIdx.x;
    for (int i = threadIdx.x; i < 10000; i += 256) h[i] = 0;
    __syncthreads();
#pragma unroll
    for (int j = threadIdx.x; j < NS; j += 256)
        atomicAdd(&h[g_n1sum[b * NS + j]], 1);
    __syncthreads();
#pragma unroll
    for (int j = threadIdx.x; j < NS; j += 256)
        w[b * NS + j] = (float)h[g_n1sum[b * NS + j]];
}

// ---------------------------------------------------------------------------
// Host: key derivation (threefry on CPU, deterministic, no device work)
// ---------------------------------------------------------------------------
static inline uint32_t h_rotl(uint32_t x, int r) {
    return (x << r) | (x >> (32 - r));
}
static void tf2x32_h(uint32_t k0, uint32_t k1, uint32_t c0, uint32_t c1,
                     uint32_t* o0, uint32_t* o1) {
    uint32_t ks2 = 0x1BD11BDAu ^ k0 ^ k1;
    uint32_t x0 = c0 + k0, x1 = c1 + k1;
#define TFH(r) { x0 += x1; x1 = h_rotl(x1, (r)); x1 ^= x0; }
    TFH(13) TFH(15) TFH(26) TFH(6)
    x0 += k1;  x1 += ks2 + 1u;
    TFH(17) TFH(29) TFH(16) TFH(24)
    x0 += ks2; x1 += k0 + 2u;
    TFH(13) TFH(15) TFH(26) TFH(6)
    x0 += k0;  x1 += k1 + 3u;
    TFH(17) TFH(29) TFH(16) TFH(24)
    x0 += k1;  x1 += ks2 + 4u;
    TFH(13) TFH(15) TFH(26) TFH(6)
    x0 += ks2; x1 += k0 + 5u;
#undef TFH
    *o0 = x0; *o1 = x1;
}

extern "C" void kernel_launch(void* const* d_in, const int* in_sizes, int n_in,
                              void* d_out, int out_size) {
    const float* n1_logits = (const float*)d_in[0];
    const float* counters  = (const float*)d_in[1];
    const int*   s_arr     = (const int*)d_in[2];
    float* out = (float*)d_out;

    // jax.random.key(42) -> (0, 42); 4x split; categorical uses the sub key.
    uint32_t kk0 = 0u, kk1 = 42u;
    uint32_t keys[8];
    for (int i = 0; i < ND; i++) {
        uint32_t nk0, nk1, sk0, sk1;
#if PARTITIONABLE
        // fold-like split: newkey = lanes(cipher(key, 0,0)); sub = lanes(cipher(key, 0,1))
        tf2x32_h(kk0, kk1, 0u, 0u, &nk0, &nk1);
        tf2x32_h(kk0, kk1, 0u, 1u, &sk0, &sk1);
#else
        // legacy split: counts [0,1,2,3] -> pairs (0,2),(1,3)
        uint32_t a0, a1, b0, b1;
        tf2x32_h(kk0, kk1, 0u, 2u, &a0, &a1);
        tf2x32_h(kk0, kk1, 1u, 3u, &b0, &b1);
        nk0 = a0; nk1 = b0; sk0 = a1; sk1 = b1;
#endif
        keys[2 * i]     = sk0;
        keys[2 * i + 1] = sk1;
        kk0 = nk0; kk1 = nk1;
    }
    uint4 ka = make_uint4(keys[0], keys[1], keys[2], keys[3]);
    uint4 kb = make_uint4(keys[4], keys[5], keys[6], keys[7]);

    dim3 grid(NS / 256, NBATCH);
    sampler_kernel<<<grid, 256>>>(n1_logits, counters, s_arr, out, ka, kb);

    float* w = out + (size_t)2 * NBATCH * NS * ND;
    hist_kernel<<<NBATCH, 256>>>(w);
}

// round 2
// speedup vs baseline: 1.2683x; 1.2683x over previous
#include <cuda_runtime.h>
#include <stdint.h>
#include <math.h>

// Problem constants
#define ND 4       // digits
#define NS 2048    // samples
#define NBATCH 512
#define ALPHA_C 0.1f

// scratch: n1_summed per (b,s)
__device__ int g_n1sum[NBATCH * NS];

// ---------------------------------------------------------------------------
// threefry2x32 (device)
// ---------------------------------------------------------------------------
__device__ __forceinline__ void tf2x32_d(uint32_t k0, uint32_t k1,
                                         uint32_t c0, uint32_t c1,
                                         uint32_t& o0, uint32_t& o1) {
    uint32_t ks2 = 0x1BD11BDAu ^ k0 ^ k1;
    uint32_t x0 = c0 + k0, x1 = c1 + k1;
#define TF_RND(r) { x0 += x1; x1 = __funnelshift_l(x1, x1, (r)); x1 ^= x0; }
    TF_RND(13) TF_RND(15) TF_RND(26) TF_RND(6)
    x0 += k1;  x1 += ks2 + 1u;
    TF_RND(17) TF_RND(29) TF_RND(16) TF_RND(24)
    x0 += ks2; x1 += k0 + 2u;
    TF_RND(13) TF_RND(15) TF_RND(26) TF_RND(6)
    x0 += k0;  x1 += k1 + 3u;
    TF_RND(17) TF_RND(29) TF_RND(16) TF_RND(24)
    x0 += k1;  x1 += ks2 + 4u;
    TF_RND(13) TF_RND(15) TF_RND(26) TF_RND(6)
    x0 += ks2; x1 += k0 + 5u;
#undef TF_RND
    o0 = x0; o1 = x1;
}

// ---------------------------------------------------------------------------
// Accurate float log (musl logf, ~1 ulp) — immune to --use_fast_math rewrites
// except the single divide (div.approx under fast math, ~2 ulp: fine at our
// flip tolerance). Valid for normal positive x.
// ---------------------------------------------------------------------------
__device__ __forceinline__ float alogf(float x) {
    uint32_t ix = __float_as_uint(x);
    ix += 0x3f800000u - 0x3f3504f3u;
    int k = (int)(ix >> 23) - 127;
    ix = (ix & 0x007fffffu) + 0x3f3504f3u;
    float xm = __uint_as_float(ix);
    float f = xm - 1.0f;
    float s = f / (2.0f + f);
    float z = s * s;
    float w = z * z;
    float t1 = w * (0.40000972152f + w * 0.24279078841f);
    float t2 = z * (0.66666662693f + w * 0.28498786688f);
    float R = t2 + t1;
    float hfsq = 0.5f * f * f;
    float dk = (float)k;
    return s * (hfsq + R) + dk * 9.0580006145e-06f - hfsq + f
           + dk * 0.69313812256f;
}

// ---------------------------------------------------------------------------
// Main sampler: one thread per (b, s). Digit chain fully unrolled.
// argmax_c (sp_c + gumbel_c)  ==  argmin_c  t_c * exp(-sp_c),
// where t_c = -log(u_c). exp(-sp_c) is precomputed per block (double-precision
// exp of the EXACT float sp the reference computes, so decision boundaries
// move only by one extra multiply rounding ~1e-7 relative).
// ---------------------------------------------------------------------------
__global__ void __launch_bounds__(256)
sampler_kernel(const float* __restrict__ n1_logits,   // [B, D, 10]
               const float* __restrict__ counters,    // [D, 10]
               const int*   __restrict__ s_arr,       // [B]
               float* __restrict__ out,
               uint4 ka, uint4 kb) {
    __shared__ float sE[ND * 10];  // exp(-sp): sp = logits - alpha*log(counters)
    __shared__ int   sd[ND];       // decimal digits of s[b]
    __shared__ int   ssv;

    const int b = blockIdx.y;
    const int t = threadIdx.x;

    if (t < ND * 10) {
        // sp computed in float EXACTLY like the reference
        float spf = n1_logits[b * (ND * 10) + t] - ALPHA_C * alogf(counters[t]);
        sE[t] = (float)exp(-(double)spf);
    }
    if (t == 0) {
        int sv = s_arr[b];
        ssv = sv;
        sd[0] = sv / 1000;
        sd[1] = (sv / 100) % 10;
        sd[2] = (sv / 10) % 10;
        sd[3] = sv % 10;
    }
    __syncthreads();

    const int sidx = blockIdx.x * 256 + t;
    const uint32_t base = (uint32_t)(b * NS + sidx) * 10u;

    const uint32_t K[8] = {ka.x, ka.y, ka.z, ka.w, kb.x, kb.y, kb.z, kb.w};

    int constraint = 0;
    int samp[ND];

#pragma unroll
    for (int i = 0; i < ND; i++) {
        const int mx = sd[i];
        const uint32_t k0 = K[2 * i], k1 = K[2 * i + 1];
        const uint32_t bk = base + k1;   // fold k1 into the counter once
        float best = 3.0e38f;
        int arg = 0;
#pragma unroll
        for (int c = 0; c < 10; c++) {
            // invalid & unconstrained -> -inf in ref: never wins, skip cipher.
            // For digit 0 this is warp-uniform (whole block shares b).
            if (constraint || c <= mx) {
                uint32_t o0, o1;
                // c0 = 0, c1 = base + c; k1 pre-added into bk
                {
                    uint32_t ks2 = 0x1BD11BDAu ^ k0 ^ k1;
                    uint32_t x0 = k0, x1 = bk + (uint32_t)c;
#define TF_RND(r) { x0 += x1; x1 = __funnelshift_l(x1, x1, (r)); x1 ^= x0; }
                    TF_RND(13) TF_RND(15) TF_RND(26) TF_RND(6)
                    x0 += k1;  x1 += ks2 + 1u;
                    TF_RND(17) TF_RND(29) TF_RND(16) TF_RND(24)
                    x0 += ks2; x1 += k0 + 2u;
                    TF_RND(13) TF_RND(15) TF_RND(26) TF_RND(6)
                    x0 += k0;  x1 += k1 + 3u;
                    TF_RND(17) TF_RND(29) TF_RND(16) TF_RND(24)
                    x0 += k1;  x1 += ks2 + 4u;
                    TF_RND(13) TF_RND(15) TF_RND(26) TF_RND(6)
                    x0 += ks2; x1 += k0 + 5u;
#undef TF_RND
                    o0 = x0; o1 = x1;
                }
                uint32_t bits = o0 ^ o1;
                // JAX uniform: u = max(bitcast(bits>>9|1.0f)-1, tiny)
                float f = __uint_as_float((bits >> 9) | 0x3f800000u) - 1.0f;
                float u = fmaxf(f, 1.17549435e-38f);
                float tt = -alogf(u);          // t = -log(u) > 0
                float v = tt * sE[i * 10 + c]; // argmin t * exp(-sp)
                if (v < best) { best = v; arg = c; }
            }
        }
        samp[i] = arg;
        constraint |= (arg != mx);
    }

    const int n1 = samp[0] * 1000 + samp[1] * 100 + samp[2] * 10 + samp[3];
    const int n2 = ssv - n1;   // in [0, 10000)

    const int lin = b * NS + sidx;
    g_n1sum[lin] = n1;

    // Output layout (float32 concat): n1_samples[B,S,D,1] | n2d[B,S,D,1] | weights[B,S]
    float4* out_n1 = (float4*)out;
    float4* out_n2 = (float4*)(out + (size_t)NBATCH * NS * ND);
    out_n1[lin] = make_float4((float)samp[0], (float)samp[1],
                              (float)samp[2], (float)samp[3]);
    // sorted-shift trick == plain decimal digits of n2
    out_n2[lin] = make_float4((float)(n2 / 1000), (float)((n2 / 100) % 10),
                              (float)((n2 / 10) % 10), (float)(n2 % 10));
}

// ---------------------------------------------------------------------------
// Per-row histogram (10^4 bins in smem) + gather -> weights
// ---------------------------------------------------------------------------
__global__ void __launch_bounds__(256)
hist_kernel(float* __restrict__ w) {
    __shared__ int h[10000];
    const int b = blockIdx.x;
    for (int i = threadIdx.x; i < 10000; i += 256) h[i] = 0;
    __syncthreads();
#pragma unroll
    for (int j = threadIdx.x; j < NS; j += 256)
        atomicAdd(&h[g_n1sum[b * NS + j]], 1);
    __syncthreads();
#pragma unroll
    for (int j = threadIdx.x; j < NS; j += 256)
        w[b * NS + j] = (float)h[g_n1sum[b * NS + j]];
}

// ---------------------------------------------------------------------------
// Host: key derivation (threefry on CPU, deterministic, no device work)
// ---------------------------------------------------------------------------
static inline uint32_t h_rotl(uint32_t x, int r) {
    return (x << r) | (x >> (32 - r));
}
static void tf2x32_h(uint32_t k0, uint32_t k1, uint32_t c0, uint32_t c1,
                     uint32_t* o0, uint32_t* o1) {
    uint32_t ks2 = 0x1BD11BDAu ^ k0 ^ k1;
    uint32_t x0 = c0 + k0, x1 = c1 + k1;
#define TFH(r) { x0 += x1; x1 = h_rotl(x1, (r)); x1 ^= x0; }
    TFH(13) TFH(15) TFH(26) TFH(6)
    x0 += k1;  x1 += ks2 + 1u;
    TFH(17) TFH(29) TFH(16) TFH(24)
    x0 += ks2; x1 += k0 + 2u;
    TFH(13) TFH(15) TFH(26) TFH(6)
    x0 += k0;  x1 += k1 + 3u;
    TFH(17) TFH(29) TFH(16) TFH(24)
    x0 += k1;  x1 += ks2 + 4u;
    TFH(13) TFH(15) TFH(26) TFH(6)
    x0 += ks2; x1 += k0 + 5u;
#undef TFH
    *o0 = x0; *o1 = x1;
}

extern "C" void kernel_launch(void* const* d_in, const int* in_sizes, int n_in,
                              void* d_out, int out_size) {
    const float* n1_logits = (const float*)d_in[0];
    const float* counters  = (const float*)d_in[1];
    const int*   s_arr     = (const int*)d_in[2];
    float* out = (float*)d_out;

    // jax.random.key(42) -> (0, 42); 4x split (partitionable mode);
    // categorical uses the sub key.
    uint32_t kk0 = 0u, kk1 = 42u;
    uint32_t keys[8];
    for (int i = 0; i < ND; i++) {
        uint32_t nk0, nk1, sk0, sk1;
        tf2x32_h(kk0, kk1, 0u, 0u, &nk0, &nk1);
        tf2x32_h(kk0, kk1, 0u, 1u, &sk0, &sk1);
        keys[2 * i]     = sk0;
        keys[2 * i + 1] = sk1;
        kk0 = nk0; kk1 = nk1;
    }
    uint4 ka = make_uint4(keys[0], keys[1], keys[2], keys[3]);
    uint4 kb = make_uint4(keys[4], keys[5], keys[6], keys[7]);

    dim3 grid(NS / 256, NBATCH);
    sampler_kernel<<<grid, 256>>>(n1_logits, counters, s_arr, out, ka, kb);

    float* w = out + (size_t)2 * NBATCH * NS * ND;
    hist_kernel<<<NBATCH, 256>>>(w);
}

// round 3
// speedup vs baseline: 1.6544x; 1.3044x over previous
#include <cuda_runtime.h>
#include <stdint.h>
#include <math.h>

// Problem constants
#define ND 4       // digits
#define NS 2048    // samples
#define NBATCH 512
#define ALPHA_C 0.1f

// scratch: n1_summed per (b,s)
__device__ int g_n1sum[NBATCH * NS];

// ---------------------------------------------------------------------------
// Accurate float log (musl logf, ~1 ulp) — used only for the 40-per-block
// counter-penalty setup, where we must match the reference's sp exactly.
// ---------------------------------------------------------------------------
__device__ __forceinline__ float alogf(float x) {
    uint32_t ix = __float_as_uint(x);
    ix += 0x3f800000u - 0x3f3504f3u;
    int k = (int)(ix >> 23) - 127;
    ix = (ix & 0x007fffffu) + 0x3f3504f3u;
    float xm = __uint_as_float(ix);
    float f = xm - 1.0f;
    float s = f / (2.0f + f);
    float z = s * s;
    float w = z * z;
    float t1 = w * (0.40000972152f + w * 0.24279078841f);
    float t2 = z * (0.66666662693f + w * 0.28498786688f);
    float R = t2 + t1;
    float hfsq = 0.5f * f * f;
    float dk = (float)k;
    return s * (hfsq + R) + dk * 9.0580006145e-06f - hfsq + f
           + dk * 0.69313812256f;
}

// ---------------------------------------------------------------------------
// Main sampler: one thread per (b, s). Digit chain fully unrolled.
//
// Reference picks argmax_c (sp_c + gumbel_c), gumbel = -log(-log u).
// Order-equivalent chain:
//   argmax sp + g  ==  argmin t_c * exp(-sp_c)   (t = -log u)
//              ==  argmin (-lg2 u) * exp(-sp_c)  (ln2 factor drops)
//              ==  argmax lg2(u_c) * E_c         (E = exp(-sp) > 0, lg2 u <= 0)
// lg2 via MUFU.LG2 (1 inst). u == 0 -> lg2 = -inf, never wins argmax, which
// matches the reference's clamp-to-tiny selection.
// ---------------------------------------------------------------------------
__global__ void __launch_bounds__(256)
sampler_kernel(const float* __restrict__ n1_logits,   // [B, D, 10]
               const float* __restrict__ counters,    // [D, 10]
               const int*   __restrict__ s_arr,       // [B]
               float* __restrict__ out,
               uint4 ka, uint4 kb) {
    __shared__ float sE[ND * 10];  // exp(-sp): sp = logits - alpha*log(counters)
    __shared__ int   sd[ND];       // decimal digits of s[b]
    __shared__ int   ssv;

    const int b = blockIdx.y;
    const int t = threadIdx.x;

    if (t < ND * 10) {
        // sp computed in float EXACTLY like the reference
        float spf = n1_logits[b * (ND * 10) + t] - ALPHA_C * alogf(counters[t]);
        sE[t] = (float)exp(-(double)spf);
    }
    if (t == 0) {
        int sv = s_arr[b];
        ssv = sv;
        sd[0] = sv / 1000;
        sd[1] = (sv / 100) % 10;
        sd[2] = (sv / 10) % 10;
        sd[3] = sv % 10;
    }
    __syncthreads();

    const int sidx = blockIdx.x * 256 + t;
    const uint32_t base = (uint32_t)(b * NS + sidx) * 10u;

    const uint32_t K[8] = {ka.x, ka.y, ka.z, ka.w, kb.x, kb.y, kb.z, kb.w};

    int constraint = 0;
    int samp[ND];

#pragma unroll
    for (int i = 0; i < ND; i++) {
        const int mx = sd[i];
        const uint32_t k0 = K[2 * i], k1 = K[2 * i + 1];
        const uint32_t bk = base + k1;   // fold k1 into the counter once
        float best = -3.0e38f;
        int arg = 0;
#pragma unroll
        for (int c = 0; c < 10; c++) {
            // invalid & unconstrained -> -inf in ref: never wins, skip cipher.
            // For digit 0 this is block-uniform (whole block shares b).
            if (constraint || c <= mx) {
                uint32_t o0, o1;
                // threefry2x32: c0 = 0, c1 = base + c; k1 pre-added into bk
                {
                    uint32_t ks2 = 0x1BD11BDAu ^ k0 ^ k1;
                    uint32_t x0 = k0, x1 = bk + (uint32_t)c;
#define TF_RND(r) { x0 += x1; x1 = __funnelshift_l(x1, x1, (r)); x1 ^= x0; }
                    TF_RND(13) TF_RND(15) TF_RND(26) TF_RND(6)
                    x0 += k1;  x1 += ks2 + 1u;
                    TF_RND(17) TF_RND(29) TF_RND(16) TF_RND(24)
                    x0 += ks2; x1 += k0 + 2u;
                    TF_RND(13) TF_RND(15) TF_RND(26) TF_RND(6)
                    x0 += k0;  x1 += k1 + 3u;
                    TF_RND(17) TF_RND(29) TF_RND(16) TF_RND(24)
                    x0 += k1;  x1 += ks2 + 4u;
                    TF_RND(13) TF_RND(15) TF_RND(26) TF_RND(6)
                    x0 += ks2; x1 += k0 + 5u;
#undef TF_RND
                    o0 = x0; o1 = x1;
                }
                uint32_t bits = o0 ^ o1;
                // JAX uniform bits -> u in [0,1)
                float u = __uint_as_float((bits >> 9) | 0x3f800000u) - 1.0f;
                float lg;
                asm("lg2.approx.f32 %0, %1;" : "=f"(lg) : "f"(u));
                float v = lg * sE[i * 10 + c];   // argmax lg2(u)*E
                if (v > best) { best = v; arg = c; }
            }
        }
        samp[i] = arg;
        constraint |= (arg != mx);
    }

    const int n1 = samp[0] * 1000 + samp[1] * 100 + samp[2] * 10 + samp[3];
    const int n2 = ssv - n1;   // in [0, 10000)

    const int lin = b * NS + sidx;
    g_n1sum[lin] = n1;

    // Output layout (float32 concat): n1_samples[B,S,D,1] | n2d[B,S,D,1] | weights[B,S]
    float4* out_n1 = (float4*)out;
    float4* out_n2 = (float4*)(out + (size_t)NBATCH * NS * ND);
    out_n1[lin] = make_float4((float)samp[0], (float)samp[1],
                              (float)samp[2], (float)samp[3]);
    // sorted-shift trick == plain decimal digits of n2
    out_n2[lin] = make_float4((float)(n2 / 1000), (float)((n2 / 100) % 10),
                              (float)((n2 / 10) % 10), (float)(n2 % 10));
}

// ---------------------------------------------------------------------------
// Per-row histogram (10^4 bins in smem) + gather -> weights
// 512 threads, vectorized clear, indices cached in registers.
// ---------------------------------------------------------------------------
__global__ void __launch_bounds__(512)
hist_kernel(float* __restrict__ w) {
    __shared__ int h[10000];
    const int b = blockIdx.x;
    int4* h4 = (int4*)h;
    for (int i = threadIdx.x; i < 2500; i += 512)
        h4[i] = make_int4(0, 0, 0, 0);
    __syncthreads();
    int v[NS / 512];
#pragma unroll
    for (int j = 0; j < NS / 512; j++) {
        v[j] = g_n1sum[b * NS + threadIdx.x + j * 512];
        atomicAdd(&h[v[j]], 1);
    }
    __syncthreads();
#pragma unroll
    for (int j = 0; j < NS / 512; j++)
        w[b * NS + threadIdx.x + j * 512] = (float)h[v[j]];
}

// ---------------------------------------------------------------------------
// Host: key derivation (threefry on CPU, deterministic, no device work)
// ---------------------------------------------------------------------------
static inline uint32_t h_rotl(uint32_t x, int r) {
    return (x << r) | (x >> (32 - r));
}
static void tf2x32_h(uint32_t k0, uint32_t k1, uint32_t c0, uint32_t c1,
                     uint32_t* o0, uint32_t* o1) {
    uint32_t ks2 = 0x1BD11BDAu ^ k0 ^ k1;
    uint32_t x0 = c0 + k0, x1 = c1 + k1;
#define TFH(r) { x0 += x1; x1 = h_rotl(x1, (r)); x1 ^= x0; }
    TFH(13) TFH(15) TFH(26) TFH(6)
    x0 += k1;  x1 += ks2 + 1u;
    TFH(17) TFH(29) TFH(16) TFH(24)
    x0 += ks2; x1 += k0 + 2u;
    TFH(13) TFH(15) TFH(26) TFH(6)
    x0 += k0;  x1 += k1 + 3u;
    TFH(17) TFH(29) TFH(16) TFH(24)
    x0 += k1;  x1 += ks2 + 4u;
    TFH(13) TFH(15) TFH(26) TFH(6)
    x0 += ks2; x1 += k0 + 5u;
#undef TFH
    *o0 = x0; *o1 = x1;
}

extern "C" void kernel_launch(void* const* d_in, const int* in_sizes, int n_in,
                              void* d_out, int out_size) {
    const float* n1_logits = (const float*)d_in[0];
    const float* counters  = (const float*)d_in[1];
    const int*   s_arr     = (const int*)d_in[2];
    float* out = (float*)d_out;

    // jax.random.key(42) -> (0, 42); 4x split (partitionable mode);
    // categorical uses the sub key.
    uint32_t kk0 = 0u, kk1 = 42u;
    uint32_t keys[8];
    for (int i = 0; i < ND; i++) {
        uint32_t nk0, nk1, sk0, sk1;
        tf2x32_h(kk0, kk1, 0u, 0u, &nk0, &nk1);
        tf2x32_h(kk0, kk1, 0u, 1u, &sk0, &sk1);
        keys[2 * i]     = sk0;
        keys[2 * i + 1] = sk1;
        kk0 = nk0; kk1 = nk1;
    }
    uint4 ka = make_uint4(keys[0], keys[1], keys[2], keys[3]);
    uint4 kb = make_uint4(keys[4], keys[5], keys[6], keys[7]);

    dim3 grid(NS / 256, NBATCH);
    sampler_kernel<<<grid, 256>>>(n1_logits, counters, s_arr, out, ka, kb);

    float* w = out + (size_t)2 * NBATCH * NS * ND;
    hist_kernel<<<NBATCH, 512>>>(w);
}